// round 6
// baseline (speedup 1.0000x reference)
#include <cuda_runtime.h>
#include <cuda_fp16.h>
#include <cstdint>

// ---------------------------------------------------------------------------
// Problem constants
// ---------------------------------------------------------------------------
#define M_TOTAL 8192
#define N_TOTAL 16384
#define K_TOTAL 4096

#define BM 128
#define BN 256
#define BK 32                          // fp16 elems per K chunk (64 B rows)
#define NCHUNK (K_TOTAL / BK)          // 128
#define STAGES 4
#define A_BYTES 8192u                  // 128 rows * 64 B
#define B_BYTES 16384u                 // 256 rows * 64 B
#define STAGE_BYTES (A_BYTES + B_BYTES)        // 24576
#define SMEM_GEMM (STAGES * STAGE_BYTES)       // 98304

// fp16 staging buffers (allocation-free scratch: __device__ globals)
__device__ __half g_x16[(size_t)M_TOTAL * K_TOTAL];   // 64 MB
__device__ __half g_w16[(size_t)N_TOTAL * K_TOTAL];   // 128 MB
__device__ int g_w_is_i32;             // weight dtype flag (detect kernel)

// ---------------------------------------------------------------------------
// Helpers
// ---------------------------------------------------------------------------
__device__ __forceinline__ uint32_t smem_u32(const void* p) {
    uint32_t r;
    asm("{ .reg .u64 t; cvta.to.shared.u64 t, %1; cvt.u32.u64 %0, t; }"
        : "=r"(r) : "l"(p));
    return r;
}

// XOR swizzle for 64-byte rows: chunk col (bits 4-5) ^= row bits 1-2.
#define SWZ(o) ((o) ^ ((((o) >> 7) & 3) << 4))

__device__ __forceinline__ void cp_async16(uint32_t dst, const void* src) {
    asm volatile("cp.async.cg.shared.global [%0], [%1], 16;\n"
                 :: "r"(dst), "l"(src));
}
#define CP_COMMIT() asm volatile("cp.async.commit_group;\n" ::: "memory")
#define CP_WAIT(n)  asm volatile("cp.async.wait_group %0;\n" :: "n"(n) : "memory")

__device__ __forceinline__ void ldsm_x4(uint32_t& r0, uint32_t& r1,
                                        uint32_t& r2, uint32_t& r3,
                                        uint32_t addr) {
    asm volatile("ldmatrix.sync.aligned.m8n8.x4.shared.b16 {%0,%1,%2,%3}, [%4];"
                 : "=r"(r0), "=r"(r1), "=r"(r2), "=r"(r3) : "r"(addr));
}

__device__ __forceinline__ void mma16816(float* d, const uint32_t* a,
                                         const uint32_t* b) {
    asm volatile(
        "mma.sync.aligned.m16n8k16.row.col.f32.f16.f16.f32 "
        "{%0,%1,%2,%3}, {%4,%5,%6,%7}, {%8,%9}, {%0,%1,%2,%3};"
        : "+f"(d[0]), "+f"(d[1]), "+f"(d[2]), "+f"(d[3])
        : "r"(a[0]), "r"(a[1]), "r"(a[2]), "r"(a[3]), "r"(b[0]), "r"(b[1]));
}

// ---------------------------------------------------------------------------
// Weight dtype detection (int8 bytes read as int32 words land in [-127,127]
// with prob ~2^-24/word; all 16384 words in range <=> int32 buffer).
// ---------------------------------------------------------------------------
__global__ void __launch_bounds__(256) detect_w_kernel(const int4* __restrict__ w) {
    __shared__ int s_out_of_range;
    if (threadIdx.x == 0) s_out_of_range = 0;
    __syncthreads();
    int bad = 0;
#pragma unroll
    for (int it = 0; it < 16; it++) {
        int4 v = w[threadIdx.x * 16 + it];
        if (v.x < -127 || v.x > 127 || v.y < -127 || v.y > 127 ||
            v.z < -127 || v.z > 127 || v.w < -127 || v.w > 127) bad = 1;
    }
    if (bad) atomicOr(&s_out_of_range, 1);
    __syncthreads();
    if (threadIdx.x == 0) g_w_is_i32 = s_out_of_range ? 0 : 1;
}

// ---------------------------------------------------------------------------
// Conversion kernels
// ---------------------------------------------------------------------------
__global__ void __launch_bounds__(256) cvt_x_kernel(const float4* __restrict__ x) {
    size_t i = (size_t)blockIdx.x * blockDim.x + threadIdx.x;
    float4 v = x[i];
    __half2 a = __floats2half2_rn(v.x, v.y);
    __half2 b = __floats2half2_rn(v.z, v.w);
    reinterpret_cast<uint2*>(g_x16)[i] =
        make_uint2(*reinterpret_cast<uint32_t*>(&a),
                   *reinterpret_cast<uint32_t*>(&b));
}

__global__ void __launch_bounds__(256) cvt_w_kernel(const void* __restrict__ wraw) {
    size_t i = (size_t)blockIdx.x * blockDim.x + threadIdx.x;
    uint32_t o[4];
    if (g_w_is_i32) {
        const int4* w = (const int4*)wraw;
        int4 v0 = w[2 * i];
        int4 v1 = w[2 * i + 1];
        __half2 h0 = __floats2half2_rn((float)v0.x, (float)v0.y);
        __half2 h1 = __floats2half2_rn((float)v0.z, (float)v0.w);
        __half2 h2 = __floats2half2_rn((float)v1.x, (float)v1.y);
        __half2 h3 = __floats2half2_rn((float)v1.z, (float)v1.w);
        o[0] = *reinterpret_cast<uint32_t*>(&h0);
        o[1] = *reinterpret_cast<uint32_t*>(&h1);
        o[2] = *reinterpret_cast<uint32_t*>(&h2);
        o[3] = *reinterpret_cast<uint32_t*>(&h3);
    } else {
        const uint2* w = (const uint2*)wraw;
        uint2 r = w[i];
#pragma unroll
        for (int h = 0; h < 2; h++) {
            uint32_t v = h ? r.y : r.x;
            __half2 a = __floats2half2_rn((float)(int8_t)(v),
                                          (float)(int8_t)(v >> 8));
            __half2 b = __floats2half2_rn((float)(int8_t)(v >> 16),
                                          (float)(int8_t)(v >> 24));
            o[2 * h]     = *reinterpret_cast<uint32_t*>(&a);
            o[2 * h + 1] = *reinterpret_cast<uint32_t*>(&b);
        }
    }
    reinterpret_cast<uint4*>(g_w16)[i] = make_uint4(o[0], o[1], o[2], o[3]);
}

// ---------------------------------------------------------------------------
// GEMM: out[M,N] = X16[M,K] @ W16[N,K]^T
// CTA 128x256, 8 warps (2M x 4N), warp tile 64x64, 4-stage cp.async,
// register double-buffered fragments (ldmatrix overlapped with MMA issue).
// ---------------------------------------------------------------------------
__global__ void __launch_bounds__(256) qlinear_gemm(
    const float* __restrict__ scale_w,
    const float* __restrict__ bias,
    float* __restrict__ out)
{
    extern __shared__ char smem[];
    const uint32_t sbase = smem_u32(smem);
    const int tid = threadIdx.x;
    const int wid = tid >> 5;
    const int lane = tid & 31;
    const int wm = wid & 1;              // 2 warps along M (64 rows each)
    const int wn = wid >> 1;             // 4 warps along N (64 cols each)

    // Grouped rasterization: 16 M-tiles per group (L2 reuse).
    const int tiles_n = N_TOTAL / BN;    // 64
    const int GH = 16;
    const int bid = blockIdx.x;
    const int group = bid / (GH * tiles_n);
    const int rem = bid % (GH * tiles_n);
    const int tile_m = group * GH + (rem % GH);
    const int tile_n = rem / GH;

    const __half* Abase = g_x16 + (size_t)tile_m * BM * K_TOTAL;
    const __half* Bbase = g_w16 + (size_t)tile_n * BN * K_TOTAL;

    auto load_chunk = [&](int c, int s) {
        uint32_t aB = sbase + (uint32_t)s * STAGE_BYTES;
        uint32_t bB = aB + A_BYTES;
        const __half* As = Abase + c * BK;
        const __half* Bs = Bbase + c * BK;
#pragma unroll
        for (int it = 0; it < 2; it++) {             // A: 512 16B loads
            int idx = tid + it * 256;
            int row = idx >> 2, seg = idx & 3;
            uint32_t off = (uint32_t)(row * 64 + seg * 16);
            cp_async16(aB + SWZ(off), As + (size_t)row * K_TOTAL + seg * 8);
        }
#pragma unroll
        for (int it = 0; it < 4; it++) {             // B: 1024 16B loads
            int idx = tid + it * 256;
            int row = idx >> 2, seg = idx & 3;
            uint32_t off = (uint32_t)(row * 64 + seg * 16);
            cp_async16(bB + SWZ(off), Bs + (size_t)row * K_TOTAL + seg * 8);
        }
    };

    // Precomputed swizzled ldmatrix offsets (loop-invariant; kills ALU work).
    const int lrow = lane & 15;
    const int lcol = (lane >> 4) << 4;   // 0 or 16 bytes
    uint32_t offA[4][2], offB[4][2];
#pragma unroll
    for (int i = 0; i < 4; i++)
#pragma unroll
        for (int t = 0; t < 2; t++) {
            uint32_t oa = (uint32_t)((wm * 64 + i * 16 + lrow) * 64 + t * 32 + lcol);
            uint32_t ob = (uint32_t)((wn * 64 + i * 16 + lrow) * 64 + t * 32 + lcol);
            offA[i][t] = SWZ(oa);
            offB[i][t] = SWZ(ob) + A_BYTES;
        }

    float acc[4][8][4];
#pragma unroll
    for (int i = 0; i < 4; i++)
#pragma unroll
        for (int j = 0; j < 8; j++)
#pragma unroll
            for (int v = 0; v < 4; v++) acc[i][j][v] = 0.f;

    // prologue: fill 3 stages
#pragma unroll
    for (int c = 0; c < STAGES - 1; c++) { load_chunk(c, c); CP_COMMIT(); }

    uint32_t a0[4][4], a1[4][4];         // double-buffered A frags
    uint32_t b0[8][2], b1[8][2];         // double-buffered B frags

    for (int c = 0; c < NCHUNK; c++) {
        CP_WAIT(STAGES - 2);             // chunk c resident
        __syncthreads();

        const uint32_t base = sbase + (uint32_t)(c & (STAGES - 1)) * STAGE_BYTES;

        // ---- issue k0 fragment loads (consumed by first MMA block) ----
#pragma unroll
        for (int i = 0; i < 4; i++)
            ldsm_x4(a0[i][0], a0[i][1], a0[i][2], a0[i][3], base + offA[i][0]);
#pragma unroll
        for (int jj = 0; jj < 4; jj++) {
            uint32_t r0, r1, r2, r3;
            ldsm_x4(r0, r1, r2, r3, base + offB[jj][0]);
            b0[2 * jj][0] = r0;     b0[2 * jj][1] = r2;
            b0[2 * jj + 1][0] = r1; b0[2 * jj + 1][1] = r3;
        }

        // ---- prefetch chunk c+3 (crossbar writes drain under k0 MMAs) ----
        if (c + STAGES - 1 < NCHUNK)
            load_chunk(c + STAGES - 1, (c + STAGES - 1) & (STAGES - 1));
        CP_COMMIT();

        // ---- issue k1 fragment loads (hidden under k0 MMA block) ----
#pragma unroll
        for (int i = 0; i < 4; i++)
            ldsm_x4(a1[i][0], a1[i][1], a1[i][2], a1[i][3], base + offA[i][1]);
#pragma unroll
        for (int jj = 0; jj < 4; jj++) {
            uint32_t r0, r1, r2, r3;
            ldsm_x4(r0, r1, r2, r3, base + offB[jj][1]);
            b1[2 * jj][0] = r0;     b1[2 * jj][1] = r2;
            b1[2 * jj + 1][0] = r1; b1[2 * jj + 1][1] = r3;
        }

        // ---- MMA k0 then k1 ----
#pragma unroll
        for (int i = 0; i < 4; i++)
#pragma unroll
            for (int j = 0; j < 8; j++)
                mma16816(acc[i][j], a0[i], b0[j]);
#pragma unroll
        for (int i = 0; i < 4; i++)
#pragma unroll
            for (int j = 0; j < 8; j++)
                mma16816(acc[i][j], a1[i], b1[j]);
    }

    // ------------------------- Epilogue -----------------------------------
    // d frag: c0=(m=g, n=2u), c1=(g, 2u+1), c2=(g+8, 2u), c3=(g+8, 2u+1)
    const int g = lane >> 2;
    const int u = lane & 3;
#pragma unroll
    for (int i = 0; i < 4; i++) {
        int row0 = tile_m * BM + wm * 64 + i * 16 + g;
#pragma unroll
        for (int j = 0; j < 8; j++) {
            int col = tile_n * BN + wn * 64 + j * 8 + 2 * u;
            float2 sc = *(const float2*)(scale_w + col);
            float2 bi = *(const float2*)(bias + col);
            float2 y0 = make_float2(acc[i][j][0] * sc.x + bi.x,
                                    acc[i][j][1] * sc.y + bi.y);
            float2 y1 = make_float2(acc[i][j][2] * sc.x + bi.x,
                                    acc[i][j][3] * sc.y + bi.y);
            *(float2*)(out + (size_t)row0 * N_TOTAL + col) = y0;
            *(float2*)(out + (size_t)(row0 + 8) * N_TOTAL + col) = y1;
        }
    }
}

// ---------------------------------------------------------------------------
// kernel_launch
// ---------------------------------------------------------------------------
extern "C" void kernel_launch(void* const* d_in, const int* in_sizes, int n_in,
                              void* d_out, int out_size) {
    const float* x = (const float*)d_in[0];
    const void* wq = d_in[1];
    const float* scale = (const float*)d_in[2];
    const float* bias = (const float*)d_in[3];
    float* out = (float*)d_out;

    detect_w_kernel<<<1, 256>>>((const int4*)wq);
    cvt_x_kernel<<<(int)((size_t)M_TOTAL * K_TOTAL / 4 / 256), 256>>>((const float4*)x);
    cvt_w_kernel<<<(int)((size_t)N_TOTAL * K_TOTAL / 8 / 256), 256>>>(wq);

    cudaFuncSetAttribute(qlinear_gemm,
                         cudaFuncAttributeMaxDynamicSharedMemorySize, SMEM_GEMM);
    const int grid = (M_TOTAL / BM) * (N_TOTAL / BN);   // 4096
    qlinear_gemm<<<grid, 256, SMEM_GEMM>>>(scale, bias, out);
}

// round 7
// speedup vs baseline: 1.3708x; 1.3708x over previous
#include <cuda_runtime.h>
#include <cuda_fp16.h>
#include <cstdint>

// ---------------------------------------------------------------------------
// Problem constants
// ---------------------------------------------------------------------------
#define M_TOTAL 8192
#define N_TOTAL 16384
#define K_TOTAL 4096

#define BM 128
#define BN 128
#define BK 64                          // fp16 elems per K chunk (128 B rows)
#define NCHUNK (K_TOTAL / BK)          // 64
#define STAGES 3
#define A_BYTES 16384u                 // 128 rows * 128 B
#define STAGE_BYTES (2u * A_BYTES)     // A + B = 32768
#define SMEM_GEMM (STAGES * STAGE_BYTES)       // 98304 -> 2 CTAs/SM

// fp16 staging buffers (allocation-free scratch: __device__ globals)
__device__ __half g_x16[(size_t)M_TOTAL * K_TOTAL];   // 64 MB
__device__ __half g_w16[(size_t)N_TOTAL * K_TOTAL];   // 128 MB
__device__ int g_w_is_i32;             // weight dtype flag (detect kernel)

// ---------------------------------------------------------------------------
// Helpers
// ---------------------------------------------------------------------------
__device__ __forceinline__ uint32_t smem_u32(const void* p) {
    uint32_t r;
    asm("{ .reg .u64 t; cvta.to.shared.u64 t, %1; cvt.u32.u64 %0, t; }"
        : "=r"(r) : "l"(p));
    return r;
}

// Classic 128-byte-row swizzle: bits[6:4] ^= bits[9:7]. XOR-linear.
#define SWZ128(o) ((o) ^ (((o) >> 3) & 0x70))

__device__ __forceinline__ void cp_async16(uint32_t dst, const void* src) {
    asm volatile("cp.async.cg.shared.global [%0], [%1], 16;\n"
                 :: "r"(dst), "l"(src));
}
#define CP_COMMIT() asm volatile("cp.async.commit_group;\n" ::: "memory")
#define CP_WAIT(n)  asm volatile("cp.async.wait_group %0;\n" :: "n"(n) : "memory")

__device__ __forceinline__ void ldsm_x4(uint32_t& r0, uint32_t& r1,
                                        uint32_t& r2, uint32_t& r3,
                                        uint32_t addr) {
    asm volatile("ldmatrix.sync.aligned.m8n8.x4.shared.b16 {%0,%1,%2,%3}, [%4];"
                 : "=r"(r0), "=r"(r1), "=r"(r2), "=r"(r3) : "r"(addr));
}

__device__ __forceinline__ void mma16816(float* d, const uint32_t* a,
                                         const uint32_t* b) {
    asm volatile(
        "mma.sync.aligned.m16n8k16.row.col.f32.f16.f16.f32 "
        "{%0,%1,%2,%3}, {%4,%5,%6,%7}, {%8,%9}, {%0,%1,%2,%3};"
        : "+f"(d[0]), "+f"(d[1]), "+f"(d[2]), "+f"(d[3])
        : "r"(a[0]), "r"(a[1]), "r"(a[2]), "r"(a[3]), "r"(b[0]), "r"(b[1]));
}

// ---------------------------------------------------------------------------
// Weight dtype detection (int8 bytes read as int32 words land in [-127,127]
// with prob ~2^-24/word; all 16384 words in range <=> int32 buffer).
// ---------------------------------------------------------------------------
__global__ void __launch_bounds__(256) detect_w_kernel(const int4* __restrict__ w) {
    __shared__ int s_out_of_range;
    if (threadIdx.x == 0) s_out_of_range = 0;
    __syncthreads();
    int bad = 0;
#pragma unroll
    for (int it = 0; it < 16; it++) {
        int4 v = w[threadIdx.x * 16 + it];
        if (v.x < -127 || v.x > 127 || v.y < -127 || v.y > 127 ||
            v.z < -127 || v.z > 127 || v.w < -127 || v.w > 127) bad = 1;
    }
    if (bad) atomicOr(&s_out_of_range, 1);
    __syncthreads();
    if (threadIdx.x == 0) g_w_is_i32 = s_out_of_range ? 0 : 1;
}

// ---------------------------------------------------------------------------
// Conversion kernels
// ---------------------------------------------------------------------------
__global__ void __launch_bounds__(256) cvt_x_kernel(const float4* __restrict__ x) {
    size_t i = (size_t)blockIdx.x * blockDim.x + threadIdx.x;
    float4 v = x[i];
    __half2 a = __floats2half2_rn(v.x, v.y);
    __half2 b = __floats2half2_rn(v.z, v.w);
    reinterpret_cast<uint2*>(g_x16)[i] =
        make_uint2(*reinterpret_cast<uint32_t*>(&a),
                   *reinterpret_cast<uint32_t*>(&b));
}

__global__ void __launch_bounds__(256) cvt_w_kernel(const void* __restrict__ wraw) {
    size_t i = (size_t)blockIdx.x * blockDim.x + threadIdx.x;
    uint32_t o[4];
    if (g_w_is_i32) {
        const int4* w = (const int4*)wraw;
        int4 v0 = w[2 * i];
        int4 v1 = w[2 * i + 1];
        __half2 h0 = __floats2half2_rn((float)v0.x, (float)v0.y);
        __half2 h1 = __floats2half2_rn((float)v0.z, (float)v0.w);
        __half2 h2 = __floats2half2_rn((float)v1.x, (float)v1.y);
        __half2 h3 = __floats2half2_rn((float)v1.z, (float)v1.w);
        o[0] = *reinterpret_cast<uint32_t*>(&h0);
        o[1] = *reinterpret_cast<uint32_t*>(&h1);
        o[2] = *reinterpret_cast<uint32_t*>(&h2);
        o[3] = *reinterpret_cast<uint32_t*>(&h3);
    } else {
        const uint2* w = (const uint2*)wraw;
        uint2 r = w[i];
#pragma unroll
        for (int h = 0; h < 2; h++) {
            uint32_t v = h ? r.y : r.x;
            __half2 a = __floats2half2_rn((float)(int8_t)(v),
                                          (float)(int8_t)(v >> 8));
            __half2 b = __floats2half2_rn((float)(int8_t)(v >> 16),
                                          (float)(int8_t)(v >> 24));
            o[2 * h]     = *reinterpret_cast<uint32_t*>(&a);
            o[2 * h + 1] = *reinterpret_cast<uint32_t*>(&b);
        }
    }
    reinterpret_cast<uint4*>(g_w16)[i] = make_uint4(o[0], o[1], o[2], o[3]);
}

// ---------------------------------------------------------------------------
// GEMM: out[M,N] = X16[M,K] @ W16[N,K]^T
// CTA 128x128, 4 warps (2M x 2N), warp tile 64x64, BK=64, 3 stages,
// 2 CTAs/SM. All smem addressing loop-invariant.
// ---------------------------------------------------------------------------
__global__ void __launch_bounds__(128, 2) qlinear_gemm(
    const float* __restrict__ scale_w,
    const float* __restrict__ bias,
    float* __restrict__ out)
{
    extern __shared__ char smem[];
    const uint32_t sbase = smem_u32(smem);
    const int tid = threadIdx.x;
    const int wid = tid >> 5;
    const int lane = tid & 31;
    const int wm = wid & 1;              // 2 warps along M (64 rows each)
    const int wn = wid >> 1;             // 2 warps along N (64 cols each)

    // Grouped rasterization: 16 M-tiles per group (L2 reuse).
    const int tiles_n = N_TOTAL / BN;    // 128
    const int GH = 16;
    const int bid = blockIdx.x;
    const int group = bid / (GH * tiles_n);
    const int rem = bid % (GH * tiles_n);
    const int tile_m = group * GH + (rem % GH);
    const int tile_n = rem / GH;

    // ---- loop-invariant cp.async addressing ----
    // 128 rows x 8 segs per operand; 128 threads -> 8 iterations, row += 16.
    const int c_row = tid >> 3;          // 0..15
    const int c_seg = tid & 7;           // 0..7
    const uint32_t dst0 = SWZ128((uint32_t)(c_row * 128 + c_seg * 16));
    const __half* srcA = g_x16 + (size_t)(tile_m * BM + c_row) * K_TOTAL + c_seg * 8;
    const __half* srcB = g_w16 + (size_t)(tile_n * BN + c_row) * K_TOTAL + c_seg * 8;

    auto load_chunk = [&](uint32_t sb) {
#pragma unroll
        for (int it = 0; it < 8; it++)
            cp_async16(sb + dst0 + it * 2048,
                       srcA + (size_t)it * 16 * K_TOTAL);
#pragma unroll
        for (int it = 0; it < 8; it++)
            cp_async16(sb + A_BYTES + dst0 + it * 2048,
                       srcB + (size_t)it * 16 * K_TOTAL);
        srcA += BK;                      // advance to next K chunk
        srcB += BK;
    };

    // ---- loop-invariant ldmatrix offsets (k-step t: addr ^= t<<5) ----
    const int lrow = lane & 15;
    const int lcol = (lane >> 4) << 4;   // 0 or 16 bytes
    uint32_t offA[4], offB[4];
#pragma unroll
    for (int i = 0; i < 4; i++) {
        offA[i] = SWZ128((uint32_t)((wm * 64 + i * 16 + lrow) * 128 + lcol));
        offB[i] = SWZ128((uint32_t)((wn * 64 + i * 16 + lrow) * 128 + lcol))
                  + A_BYTES;
    }

    float acc[4][8][4];
#pragma unroll
    for (int i = 0; i < 4; i++)
#pragma unroll
        for (int j = 0; j < 8; j++)
#pragma unroll
            for (int v = 0; v < 4; v++) acc[i][j][v] = 0.f;

    // prologue: fill 2 stages
    load_chunk(sbase);              CP_COMMIT();
    load_chunk(sbase + STAGE_BYTES); CP_COMMIT();

    uint32_t st_cur = 0;                        // current stage offset
    uint32_t st_pre = 2 * STAGE_BYTES;          // prefetch stage offset

    for (int c = 0; c < NCHUNK; c++) {
        CP_WAIT(1);                  // chunk c resident
        __syncthreads();

        if (c + 2 < NCHUNK) load_chunk(sbase + st_pre);
        CP_COMMIT();
        st_pre += STAGE_BYTES; if (st_pre == STAGES * STAGE_BYTES) st_pre = 0;

        const uint32_t base = sbase + st_cur;
        st_cur += STAGE_BYTES; if (st_cur == STAGES * STAGE_BYTES) st_cur = 0;

#pragma unroll
        for (int t = 0; t < 4; t++) {    // four k16 steps per chunk
            const uint32_t tx = (uint32_t)(t << 5);
            uint32_t a[4][4];
            uint32_t b[8][2];
#pragma unroll
            for (int i = 0; i < 4; i++)
                ldsm_x4(a[i][0], a[i][1], a[i][2], a[i][3],
                        base + (offA[i] ^ tx));
#pragma unroll
            for (int jj = 0; jj < 4; jj++) {
                uint32_t r0, r1, r2, r3;
                ldsm_x4(r0, r1, r2, r3, base + (offB[jj] ^ tx));
                b[2 * jj][0] = r0;     b[2 * jj][1] = r2;
                b[2 * jj + 1][0] = r1; b[2 * jj + 1][1] = r3;
            }
#pragma unroll
            for (int i = 0; i < 4; i++)
#pragma unroll
                for (int j = 0; j < 8; j++)
                    mma16816(acc[i][j], a[i], b[j]);
        }
    }

    // ------------------------- Epilogue -----------------------------------
    // d frag: c0=(m=g, n=2u), c1=(g, 2u+1), c2=(g+8, 2u), c3=(g+8, 2u+1)
    const int g = lane >> 2;
    const int u = lane & 3;
#pragma unroll
    for (int i = 0; i < 4; i++) {
        int row0 = tile_m * BM + wm * 64 + i * 16 + g;
#pragma unroll
        for (int j = 0; j < 8; j++) {
            int col = tile_n * BN + wn * 64 + j * 8 + 2 * u;
            float2 sc = *(const float2*)(scale_w + col);
            float2 bi = *(const float2*)(bias + col);
            float2 y0 = make_float2(acc[i][j][0] * sc.x + bi.x,
                                    acc[i][j][1] * sc.y + bi.y);
            float2 y1 = make_float2(acc[i][j][2] * sc.x + bi.x,
                                    acc[i][j][3] * sc.y + bi.y);
            *(float2*)(out + (size_t)row0 * N_TOTAL + col) = y0;
            *(float2*)(out + (size_t)(row0 + 8) * N_TOTAL + col) = y1;
        }
    }
}

// ---------------------------------------------------------------------------
// kernel_launch
// ---------------------------------------------------------------------------
extern "C" void kernel_launch(void* const* d_in, const int* in_sizes, int n_in,
                              void* d_out, int out_size) {
    const float* x = (const float*)d_in[0];
    const void* wq = d_in[1];
    const float* scale = (const float*)d_in[2];
    const float* bias = (const float*)d_in[3];
    float* out = (float*)d_out;

    detect_w_kernel<<<1, 256>>>((const int4*)wq);
    cvt_x_kernel<<<(int)((size_t)M_TOTAL * K_TOTAL / 4 / 256), 256>>>((const float4*)x);
    cvt_w_kernel<<<(int)((size_t)N_TOTAL * K_TOTAL / 8 / 256), 256>>>(wq);

    cudaFuncSetAttribute(qlinear_gemm,
                         cudaFuncAttributeMaxDynamicSharedMemorySize, SMEM_GEMM);
    const int grid = (M_TOTAL / BM) * (N_TOTAL / BN);   // 8192
    qlinear_gemm<<<grid, 128, SMEM_GEMM>>>(scale, bias, out);
}